// round 2
// baseline (speedup 1.0000x reference)
#include <cuda_runtime.h>
#include <math.h>

#define N_TOK 8192
#define D_DIM 512
#define F_DIM 2048
#define E_NUM 8
#define ASSIGN (2 * N_TOK)

#define BM 64
#define BN 64
#define BK 32

#define EPS_F 2.2204460492503131e-16f

// ---- scratch (allocation-free: __device__ globals) ----
__device__ float g_h[(size_t)ASSIGN * F_DIM];      // 128 MB: relu(h) per assignment
__device__ float g_acc[(size_t)N_TOK * D_DIM];     // 16 MB: combine accumulator
__device__ int   g_e0[N_TOK];
__device__ int   g_e1[N_TOK];
__device__ float g_g0[N_TOK];
__device__ float g_g1[N_TOK];
__device__ int   g_cnt[E_NUM];
__device__ int   g_off[E_NUM];
__device__ int   g_cur[E_NUM];
__device__ int   g_tok[ASSIGN];
__device__ float g_gate[ASSIGN];

// ---- init: zero accumulator + counters ----
__global__ void k_init() {
    size_t i = (size_t)blockIdx.x * blockDim.x + threadIdx.x;
    if (i < (size_t)N_TOK * D_DIM) g_acc[i] = 0.f;
    if (i < E_NUM) { g_cnt[i] = 0; g_cur[i] = 0; }
}

// ---- gating: one warp per token ----
__global__ void k_gate(const float* __restrict__ x, const float* __restrict__ Wg) {
    int gt   = blockIdx.x * blockDim.x + threadIdx.x;
    int warp = gt >> 5;
    int lane = gt & 31;
    if (warp >= N_TOK) return;
    const float* xr = x + (size_t)warp * D_DIM;
    float acc[E_NUM];
#pragma unroll
    for (int e = 0; e < E_NUM; e++) acc[e] = 0.f;
    for (int d = lane; d < D_DIM; d += 32) {
        float xv = xr[d];
        const float* wr = Wg + (size_t)d * E_NUM;
#pragma unroll
        for (int e = 0; e < E_NUM; e++) acc[e] += xv * wr[e];
    }
#pragma unroll
    for (int e = 0; e < E_NUM; e++) {
#pragma unroll
        for (int off = 16; off > 0; off >>= 1)
            acc[e] += __shfl_down_sync(0xffffffffu, acc[e], off);
    }
    if (lane == 0) {
        int e0 = 0; float v0 = acc[0];
#pragma unroll
        for (int e = 1; e < E_NUM; e++)
            if (acc[e] > v0) { v0 = acc[e]; e0 = e; }
        int e1 = -1; float v1 = -INFINITY;
#pragma unroll
        for (int e = 0; e < E_NUM; e++)
            if (e != e0 && acc[e] > v1) { v1 = acc[e]; e1 = e; }
        float t  = expf(v1 - v0);        // v1 <= v0, stable
        float g0 = 1.f / (1.f + t);
        float g1 = t * g0;
        g_e0[warp] = e0; g_e1[warp] = e1;
        g_g0[warp] = g0; g_g1[warp] = g1;
        atomicAdd(&g_cnt[e0], 1);
        atomicAdd(&g_cnt[e1], 1);
    }
}

// ---- exclusive prefix over 8 counts ----
__global__ void k_off() {
    if (threadIdx.x == 0) {
        int s = 0;
        for (int e = 0; e < E_NUM; e++) { g_off[e] = s; s += g_cnt[e]; }
    }
}

// ---- scatter tokens into per-expert buckets ----
__global__ void k_scatter() {
    int n = blockIdx.x * blockDim.x + threadIdx.x;
    if (n >= N_TOK) return;
    int e0 = g_e0[n], e1 = g_e1[n];
    int s0 = atomicAdd(&g_cur[e0], 1);
    int s1 = atomicAdd(&g_cur[e1], 1);
    int p0 = g_off[e0] + s0;
    int p1 = g_off[e1] + s1;
    g_tok[p0] = n; g_gate[p0] = g_g0[n];
    g_tok[p1] = n; g_gate[p1] = g_g1[n];
}

// ---- GEMM1: h = relu(X[bucket] @ W1[e] + b1[e])  [cnt, D] x [D, F] ----
__global__ void k_gemm1(const float* __restrict__ x, const float* __restrict__ W1,
                        const float* __restrict__ b1) {
    int e = blockIdx.z;
    int cnt = g_cnt[e];
    int row0 = blockIdx.x * BM;
    if (row0 >= cnt) return;
    int base = g_off[e];
    int f0 = blockIdx.y * BN;

    __shared__ float As[BK][BM + 4];   // stride 68 floats (16B aligned)
    __shared__ float Bs[BK][BN];
    __shared__ int   toks[BM];

    int tx = threadIdx.x, ty = threadIdx.y;
    int tid = ty * 16 + tx;
    if (tid < BM) {
        int r = row0 + tid;
        toks[tid] = (r < cnt) ? g_tok[base + r] : -1;
    }
    __syncthreads();

    float c[4][4] = {};
    const float* Wb = W1 + (size_t)e * D_DIM * F_DIM;

    for (int k0 = 0; k0 < D_DIM; k0 += BK) {
        // load As (gathered x rows), k contiguous per row
#pragma unroll
        for (int it = 0; it < (BM * BK) / 256; it++) {
            int i = tid + it * 256;
            int m = i >> 5, k = i & 31;
            int t = toks[m];
            As[k][m] = (t >= 0) ? x[(size_t)t * D_DIM + k0 + k] : 0.f;
        }
        // load Bs, f contiguous
#pragma unroll
        for (int it = 0; it < (BK * BN) / 256; it++) {
            int i = tid + it * 256;
            int k = i >> 6, f = i & 63;
            Bs[k][f] = Wb[(size_t)(k0 + k) * F_DIM + f0 + f];
        }
        __syncthreads();
#pragma unroll
        for (int k = 0; k < BK; k++) {
            float4 a = *(const float4*)&As[k][ty * 4];
            float4 b = *(const float4*)&Bs[k][tx * 4];
            c[0][0] += a.x * b.x; c[0][1] += a.x * b.y; c[0][2] += a.x * b.z; c[0][3] += a.x * b.w;
            c[1][0] += a.y * b.x; c[1][1] += a.y * b.y; c[1][2] += a.y * b.z; c[1][3] += a.y * b.w;
            c[2][0] += a.z * b.x; c[2][1] += a.z * b.y; c[2][2] += a.z * b.z; c[2][3] += a.z * b.w;
            c[3][0] += a.w * b.x; c[3][1] += a.w * b.y; c[3][2] += a.w * b.z; c[3][3] += a.w * b.w;
        }
        __syncthreads();
    }

#pragma unroll
    for (int i = 0; i < 4; i++) {
        int r = row0 + ty * 4 + i;
        if (r < cnt) {
#pragma unroll
            for (int j = 0; j < 4; j++) {
                int f = f0 + tx * 4 + j;
                float v = c[i][j] + b1[e * F_DIM + f];
                g_h[(size_t)(base + r) * F_DIM + f] = fmaxf(v, 0.f);
            }
        }
    }
}

// ---- GEMM2: o = h @ W2[e] + b2[e]; acc[token] += gate * exp(o) ----
__global__ void k_gemm2(const float* __restrict__ W2, const float* __restrict__ b2) {
    int e = blockIdx.z;
    int cnt = g_cnt[e];
    int row0 = blockIdx.x * BM;
    if (row0 >= cnt) return;
    int base = g_off[e];
    int d0 = blockIdx.y * BN;

    __shared__ float As[BK][BM + 4];
    __shared__ float Bs[BK][BN];
    __shared__ int   toks[BM];
    __shared__ float gts[BM];

    int tx = threadIdx.x, ty = threadIdx.y;
    int tid = ty * 16 + tx;
    if (tid < BM) {
        int r = row0 + tid;
        toks[tid] = (r < cnt) ? g_tok[base + r] : -1;
        gts[tid]  = (r < cnt) ? g_gate[base + r] : 0.f;
    }
    __syncthreads();

    float c[4][4] = {};
    const float* Wb = W2 + (size_t)e * F_DIM * D_DIM;

    for (int k0 = 0; k0 < F_DIM; k0 += BK) {
        // load As from g_h (rows contiguous in bucket order)
#pragma unroll
        for (int it = 0; it < (BM * BK) / 256; it++) {
            int i = tid + it * 256;
            int m = i >> 5, k = i & 31;
            int r = row0 + m;
            As[k][m] = (r < cnt) ? g_h[(size_t)(base + r) * F_DIM + k0 + k] : 0.f;
        }
#pragma unroll
        for (int it = 0; it < (BK * BN) / 256; it++) {
            int i = tid + it * 256;
            int k = i >> 6, d = i & 63;
            Bs[k][d] = Wb[(size_t)(k0 + k) * D_DIM + d0 + d];
        }
        __syncthreads();
#pragma unroll
        for (int k = 0; k < BK; k++) {
            float4 a = *(const float4*)&As[k][ty * 4];
            float4 b = *(const float4*)&Bs[k][tx * 4];
            c[0][0] += a.x * b.x; c[0][1] += a.x * b.y; c[0][2] += a.x * b.z; c[0][3] += a.x * b.w;
            c[1][0] += a.y * b.x; c[1][1] += a.y * b.y; c[1][2] += a.y * b.z; c[1][3] += a.y * b.w;
            c[2][0] += a.z * b.x; c[2][1] += a.z * b.y; c[2][2] += a.z * b.z; c[2][3] += a.z * b.w;
            c[3][0] += a.w * b.x; c[3][1] += a.w * b.y; c[3][2] += a.w * b.z; c[3][3] += a.w * b.w;
        }
        __syncthreads();
    }

#pragma unroll
    for (int i = 0; i < 4; i++) {
        int r = row0 + ty * 4 + i;
        if (r < cnt) {
            int tok = toks[ty * 4 + i];
            float g = gts[ty * 4 + i];
#pragma unroll
            for (int j = 0; j < 4; j++) {
                int d = d0 + tx * 4 + j;
                float o = c[i][j] + b2[e * D_DIM + d];
                atomicAdd(&g_acc[(size_t)tok * D_DIM + d], g * expf(o));
            }
        }
    }
}

// ---- finalize: log with eps floor ----
__global__ void k_fin(float* __restrict__ out) {
    size_t i = (size_t)blockIdx.x * blockDim.x + threadIdx.x;
    if (i < (size_t)N_TOK * D_DIM) {
        float a = g_acc[i];
        out[i] = logf(a == 0.f ? EPS_F : a);
    }
}

extern "C" void kernel_launch(void* const* d_in, const int* in_sizes, int n_in,
                              void* d_out, int out_size) {
    const float* x  = (const float*)d_in[0];
    const float* Wg = (const float*)d_in[1];
    const float* W1 = (const float*)d_in[2];
    const float* b1 = (const float*)d_in[3];
    const float* W2 = (const float*)d_in[4];
    const float* b2 = (const float*)d_in[5];
    float* out = (float*)d_out;

    int nElem = N_TOK * D_DIM;

    k_init<<<(nElem + 255) / 256, 256>>>();
    k_gate<<<(N_TOK * 32 + 255) / 256, 256>>>(x, Wg);
    k_off<<<1, 32>>>();
    k_scatter<<<(N_TOK + 255) / 256, 256>>>();

    dim3 blk(16, 16);
    k_gemm1<<<dim3(N_TOK / BM, F_DIM / BN, E_NUM), blk>>>(x, W1, b1);
    k_gemm2<<<dim3(N_TOK / BM, D_DIM / BN, E_NUM), blk>>>(W2, b2);

    k_fin<<<(nElem + 255) / 256, 256>>>(out);
}

// round 3
// speedup vs baseline: 2.1810x; 2.1810x over previous
#include <cuda_runtime.h>
#include <cuda_fp16.h>
#include <math.h>

#define N_TOK 8192
#define D_DIM 512
#define F_DIM 2048
#define E_NUM 8
#define ASSIGN (2 * N_TOK)

#define BM 64
#define BN 64
#define BK 32
#define THREADS 128

#define EPS_F 2.2204460492503131e-16f

// ---- scratch (allocation-free: __device__ globals) ----
__device__ __half g_hh[(size_t)ASSIGN * F_DIM];    // 64 MB: hi half of relu(h)
__device__ __half g_hl[(size_t)ASSIGN * F_DIM];    // 64 MB: lo half of relu(h)
__device__ float g_acc[(size_t)N_TOK * D_DIM];     // 16 MB: combine accumulator
__device__ int   g_e0[N_TOK];
__device__ int   g_e1[N_TOK];
__device__ float g_g0[N_TOK];
__device__ float g_g1[N_TOK];
__device__ int   g_cnt[E_NUM];
__device__ int   g_off[E_NUM];
__device__ int   g_cur[E_NUM];
__device__ int   g_tok[ASSIGN];
__device__ float g_gate[ASSIGN];

// ---- init: zero accumulator + counters ----
__global__ void k_init() {
    size_t i = (size_t)blockIdx.x * blockDim.x + threadIdx.x;
    if (i < (size_t)N_TOK * D_DIM) g_acc[i] = 0.f;
    if (i < E_NUM) { g_cnt[i] = 0; g_cur[i] = 0; }
}

// ---- gating: one warp per token ----
__global__ void k_gate(const float* __restrict__ x, const float* __restrict__ Wg) {
    int gt   = blockIdx.x * blockDim.x + threadIdx.x;
    int warp = gt >> 5;
    int lane = gt & 31;
    if (warp >= N_TOK) return;
    const float* xr = x + (size_t)warp * D_DIM;
    float acc[E_NUM];
#pragma unroll
    for (int e = 0; e < E_NUM; e++) acc[e] = 0.f;
    for (int d = lane; d < D_DIM; d += 32) {
        float xv = xr[d];
        const float* wr = Wg + (size_t)d * E_NUM;
#pragma unroll
        for (int e = 0; e < E_NUM; e++) acc[e] += xv * wr[e];
    }
#pragma unroll
    for (int e = 0; e < E_NUM; e++) {
#pragma unroll
        for (int off = 16; off > 0; off >>= 1)
            acc[e] += __shfl_down_sync(0xffffffffu, acc[e], off);
    }
    if (lane == 0) {
        int e0 = 0; float v0 = acc[0];
#pragma unroll
        for (int e = 1; e < E_NUM; e++)
            if (acc[e] > v0) { v0 = acc[e]; e0 = e; }
        int e1 = -1; float v1 = -INFINITY;
#pragma unroll
        for (int e = 0; e < E_NUM; e++)
            if (e != e0 && acc[e] > v1) { v1 = acc[e]; e1 = e; }
        float t  = expf(v1 - v0);        // v1 <= v0, stable
        float g0 = 1.f / (1.f + t);
        float g1 = t * g0;
        g_e0[warp] = e0; g_e1[warp] = e1;
        g_g0[warp] = g0; g_g1[warp] = g1;
        atomicAdd(&g_cnt[e0], 1);
        atomicAdd(&g_cnt[e1], 1);
    }
}

// ---- exclusive prefix over 8 counts ----
__global__ void k_off() {
    if (threadIdx.x == 0) {
        int s = 0;
        for (int e = 0; e < E_NUM; e++) { g_off[e] = s; s += g_cnt[e]; }
    }
}

// ---- scatter tokens into per-expert buckets ----
__global__ void k_scatter() {
    int n = blockIdx.x * blockDim.x + threadIdx.x;
    if (n >= N_TOK) return;
    int e0 = g_e0[n], e1 = g_e1[n];
    int s0 = atomicAdd(&g_cur[e0], 1);
    int s1 = atomicAdd(&g_cur[e1], 1);
    int p0 = g_off[e0] + s0;
    int p1 = g_off[e1] + s1;
    g_tok[p0] = n; g_gate[p0] = g_g0[n];
    g_tok[p1] = n; g_gate[p1] = g_g1[n];
}

// ---- fp16 MMA helper ----
__device__ __forceinline__ void mma16816(float* c, const unsigned* a, const unsigned* b) {
    asm volatile(
        "mma.sync.aligned.m16n8k16.row.col.f32.f16.f16.f32 "
        "{%0,%1,%2,%3}, {%4,%5,%6,%7}, {%8,%9}, {%0,%1,%2,%3};\n"
        : "+f"(c[0]), "+f"(c[1]), "+f"(c[2]), "+f"(c[3])
        : "r"(a[0]), "r"(a[1]), "r"(a[2]), "r"(a[3]), "r"(b[0]), "r"(b[1]));
}

__device__ __forceinline__ void split_f32(float v, __half& hi, __half& lo) {
    hi = __float2half_rn(v);
    lo = __float2half_rn(v - __half2float(hi));
}

// SMEM layout strides (in half2 units)
#define SA_STRIDE 20   // BK/2 (=16) + 4 pad  -> conflict-free frag loads
#define SB_STRIDE 72   // BN (=64) + 8 pad    -> conflict-free frag loads

// ---- GEMM1: h = relu(X[bucket] @ W1[e] + b1[e]); store hi/lo halves ----
__global__ __launch_bounds__(THREADS)
void k_gemm1(const float* __restrict__ x, const float* __restrict__ W1,
             const float* __restrict__ b1) {
    int e = blockIdx.z;
    int cnt = g_cnt[e];
    int row0 = blockIdx.x * BM;
    if (row0 >= cnt) return;
    int base = g_off[e];
    int f0 = blockIdx.y * BN;

    __shared__ __half2 sAh[BM * SA_STRIDE];
    __shared__ __half2 sAl[BM * SA_STRIDE];
    __shared__ __half2 sBh[(BK / 2) * SB_STRIDE];
    __shared__ __half2 sBl[(BK / 2) * SB_STRIDE];
    __shared__ int toks[BM];

    int tid  = threadIdx.x;
    int lane = tid & 31;
    int wid  = tid >> 5;
    int wm = wid >> 1, wn = wid & 1;
    int g = lane >> 2, t = lane & 3;

    if (tid < BM) {
        int r = row0 + tid;
        toks[tid] = (r < cnt) ? g_tok[base + r] : -1;
    }
    __syncthreads();

    float acc[2][4][4] = {};
    const float* Wb = W1 + (size_t)e * D_DIM * F_DIM;

    for (int k0 = 0; k0 < D_DIM; k0 += BK) {
        // A: gathered x rows -> hi/lo half2 (k-pairs)
#pragma unroll
        for (int it = 0; it < (BM * BK / 2) / THREADS; it++) {
            int i = tid + it * THREADS;
            int m = i >> 4, k2 = i & 15;
            int tok = toks[m];
            float2 v = make_float2(0.f, 0.f);
            if (tok >= 0) v = *(const float2*)&x[(size_t)tok * D_DIM + k0 + 2 * k2];
            __half hx, lx, hy, ly;
            split_f32(v.x, hx, lx);
            split_f32(v.y, hy, ly);
            sAh[m * SA_STRIDE + k2] = __halves2half2(hx, hy);
            sAl[m * SA_STRIDE + k2] = __halves2half2(lx, ly);
        }
        // B: W1 rows k0+2k2, k0+2k2+1 -> hi/lo half2
#pragma unroll
        for (int it = 0; it < ((BK / 2) * BN) / THREADS; it++) {
            int i = tid + it * THREADS;
            int k2 = i >> 6, n = i & 63;
            const float* p = Wb + (size_t)(k0 + 2 * k2) * F_DIM + f0 + n;
            float v0 = p[0], v1 = p[F_DIM];
            __half h0, l0, h1, l1;
            split_f32(v0, h0, l0);
            split_f32(v1, h1, l1);
            sBh[k2 * SB_STRIDE + n] = __halves2half2(h0, h1);
            sBl[k2 * SB_STRIDE + n] = __halves2half2(l0, l1);
        }
        __syncthreads();

#pragma unroll
        for (int kt = 0; kt < 2; kt++) {
            unsigned ah[2][4], al[2][4], bh[4][2], bl[4][2];
#pragma unroll
            for (int mt = 0; mt < 2; mt++) {
                int rb = (wm * 32 + mt * 16) * SA_STRIDE + kt * 8 + t;
                ah[mt][0] = *(const unsigned*)&sAh[rb + g * SA_STRIDE];
                ah[mt][1] = *(const unsigned*)&sAh[rb + (g + 8) * SA_STRIDE];
                ah[mt][2] = *(const unsigned*)&sAh[rb + g * SA_STRIDE + 4];
                ah[mt][3] = *(const unsigned*)&sAh[rb + (g + 8) * SA_STRIDE + 4];
                al[mt][0] = *(const unsigned*)&sAl[rb + g * SA_STRIDE];
                al[mt][1] = *(const unsigned*)&sAl[rb + (g + 8) * SA_STRIDE];
                al[mt][2] = *(const unsigned*)&sAl[rb + g * SA_STRIDE + 4];
                al[mt][3] = *(const unsigned*)&sAl[rb + (g + 8) * SA_STRIDE + 4];
            }
#pragma unroll
            for (int nt = 0; nt < 4; nt++) {
                int cb = wn * 32 + nt * 8 + g;
                bh[nt][0] = *(const unsigned*)&sBh[(kt * 8 + t) * SB_STRIDE + cb];
                bh[nt][1] = *(const unsigned*)&sBh[(kt * 8 + t + 4) * SB_STRIDE + cb];
                bl[nt][0] = *(const unsigned*)&sBl[(kt * 8 + t) * SB_STRIDE + cb];
                bl[nt][1] = *(const unsigned*)&sBl[(kt * 8 + t + 4) * SB_STRIDE + cb];
            }
#pragma unroll
            for (int mt = 0; mt < 2; mt++)
#pragma unroll
                for (int nt = 0; nt < 4; nt++) {
                    mma16816(acc[mt][nt], ah[mt], bh[nt]);
                    mma16816(acc[mt][nt], ah[mt], bl[nt]);
                    mma16816(acc[mt][nt], al[mt], bh[nt]);
                }
        }
        __syncthreads();
    }

    // epilogue: +bias, relu, split to hi/lo halves
#pragma unroll
    for (int mt = 0; mt < 2; mt++) {
#pragma unroll
        for (int nt = 0; nt < 4; nt++) {
            int row = wm * 32 + mt * 16 + g;
            int col = wn * 32 + nt * 8 + t * 2;
            int f = f0 + col;
            float bb0 = b1[e * F_DIM + f];
            float bb1 = b1[e * F_DIM + f + 1];
            int r0 = row0 + row;
            if (r0 < cnt) {
                float v0 = fmaxf(acc[mt][nt][0] + bb0, 0.f);
                float v1 = fmaxf(acc[mt][nt][1] + bb1, 0.f);
                __half h0, l0, h1, l1;
                split_f32(v0, h0, l0);
                split_f32(v1, h1, l1);
                size_t o = (size_t)(base + r0) * F_DIM + f;
                *(__half2*)&g_hh[o] = __halves2half2(h0, h1);
                *(__half2*)&g_hl[o] = __halves2half2(l0, l1);
            }
            int r1 = row0 + row + 8;
            if (r1 < cnt) {
                float v0 = fmaxf(acc[mt][nt][2] + bb0, 0.f);
                float v1 = fmaxf(acc[mt][nt][3] + bb1, 0.f);
                __half h0, l0, h1, l1;
                split_f32(v0, h0, l0);
                split_f32(v1, h1, l1);
                size_t o = (size_t)(base + r1) * F_DIM + f;
                *(__half2*)&g_hh[o] = __halves2half2(h0, h1);
                *(__half2*)&g_hl[o] = __halves2half2(l0, l1);
            }
        }
    }
}

// ---- GEMM2: o = h @ W2[e] + b2[e]; acc[token] += gate * exp(o) ----
__global__ __launch_bounds__(THREADS)
void k_gemm2(const float* __restrict__ W2, const float* __restrict__ b2) {
    int e = blockIdx.z;
    int cnt = g_cnt[e];
    int row0 = blockIdx.x * BM;
    if (row0 >= cnt) return;
    int base = g_off[e];
    int d0 = blockIdx.y * BN;

    __shared__ __half2 sAh[BM * SA_STRIDE];
    __shared__ __half2 sAl[BM * SA_STRIDE];
    __shared__ __half2 sBh[(BK / 2) * SB_STRIDE];
    __shared__ __half2 sBl[(BK / 2) * SB_STRIDE];
    __shared__ int   toks[BM];
    __shared__ float gts[BM];

    int tid  = threadIdx.x;
    int lane = tid & 31;
    int wid  = tid >> 5;
    int wm = wid >> 1, wn = wid & 1;
    int g = lane >> 2, t = lane & 3;

    if (tid < BM) {
        int r = row0 + tid;
        toks[tid] = (r < cnt) ? g_tok[base + r] : -1;
        gts[tid]  = (r < cnt) ? g_gate[base + r] : 0.f;
    }
    __syncthreads();

    float acc[2][4][4] = {};
    const float* Wb = W2 + (size_t)e * F_DIM * D_DIM;

    for (int k0 = 0; k0 < F_DIM; k0 += BK) {
        // A: pre-split h (already halves, no conversion)
#pragma unroll
        for (int it = 0; it < (BM * BK / 2) / THREADS; it++) {
            int i = tid + it * THREADS;
            int m = i >> 4, k2 = i & 15;
            int r = row0 + m;
            __half2 vh = __halves2half2(__float2half(0.f), __float2half(0.f));
            __half2 vl = vh;
            if (r < cnt) {
                size_t o = (size_t)(base + r) * F_DIM + k0 + 2 * k2;
                vh = *(const __half2*)&g_hh[o];
                vl = *(const __half2*)&g_hl[o];
            }
            sAh[m * SA_STRIDE + k2] = vh;
            sAl[m * SA_STRIDE + k2] = vl;
        }
        // B: W2 rows -> hi/lo half2
#pragma unroll
        for (int it = 0; it < ((BK / 2) * BN) / THREADS; it++) {
            int i = tid + it * THREADS;
            int k2 = i >> 6, n = i & 63;
            const float* p = Wb + (size_t)(k0 + 2 * k2) * D_DIM + d0 + n;
            float v0 = p[0], v1 = p[D_DIM];
            __half h0, l0, h1, l1;
            split_f32(v0, h0, l0);
            split_f32(v1, h1, l1);
            sBh[k2 * SB_STRIDE + n] = __halves2half2(h0, h1);
            sBl[k2 * SB_STRIDE + n] = __halves2half2(l0, l1);
        }
        __syncthreads();

#pragma unroll
        for (int kt = 0; kt < 2; kt++) {
            unsigned ah[2][4], al[2][4], bh[4][2], bl[4][2];
#pragma unroll
            for (int mt = 0; mt < 2; mt++) {
                int rb = (wm * 32 + mt * 16) * SA_STRIDE + kt * 8 + t;
                ah[mt][0] = *(const unsigned*)&sAh[rb + g * SA_STRIDE];
                ah[mt][1] = *(const unsigned*)&sAh[rb + (g + 8) * SA_STRIDE];
                ah[mt][2] = *(const unsigned*)&sAh[rb + g * SA_STRIDE + 4];
                ah[mt][3] = *(const unsigned*)&sAh[rb + (g + 8) * SA_STRIDE + 4];
                al[mt][0] = *(const unsigned*)&sAl[rb + g * SA_STRIDE];
                al[mt][1] = *(const unsigned*)&sAl[rb + (g + 8) * SA_STRIDE];
                al[mt][2] = *(const unsigned*)&sAl[rb + g * SA_STRIDE + 4];
                al[mt][3] = *(const unsigned*)&sAl[rb + (g + 8) * SA_STRIDE + 4];
            }
#pragma unroll
            for (int nt = 0; nt < 4; nt++) {
                int cb = wn * 32 + nt * 8 + g;
                bh[nt][0] = *(const unsigned*)&sBh[(kt * 8 + t) * SB_STRIDE + cb];
                bh[nt][1] = *(const unsigned*)&sBh[(kt * 8 + t + 4) * SB_STRIDE + cb];
                bl[nt][0] = *(const unsigned*)&sBl[(kt * 8 + t) * SB_STRIDE + cb];
                bl[nt][1] = *(const unsigned*)&sBl[(kt * 8 + t + 4) * SB_STRIDE + cb];
            }
#pragma unroll
            for (int mt = 0; mt < 2; mt++)
#pragma unroll
                for (int nt = 0; nt < 4; nt++) {
                    mma16816(acc[mt][nt], ah[mt], bh[nt]);
                    mma16816(acc[mt][nt], ah[mt], bl[nt]);
                    mma16816(acc[mt][nt], al[mt], bh[nt]);
                }
        }
        __syncthreads();
    }

    // epilogue: +bias, gate*exp, atomic combine
#pragma unroll
    for (int mt = 0; mt < 2; mt++) {
#pragma unroll
        for (int nt = 0; nt < 4; nt++) {
            int row = wm * 32 + mt * 16 + g;
            int col = wn * 32 + nt * 8 + t * 2;
            int d = d0 + col;
            float bb0 = b2[e * D_DIM + d];
            float bb1 = b2[e * D_DIM + d + 1];
            int r0 = row0 + row;
            if (r0 < cnt) {
                int tok = toks[row];
                float gv = gts[row];
                atomicAdd(&g_acc[(size_t)tok * D_DIM + d],     gv * expf(acc[mt][nt][0] + bb0));
                atomicAdd(&g_acc[(size_t)tok * D_DIM + d + 1], gv * expf(acc[mt][nt][1] + bb1));
            }
            int r1 = row0 + row + 8;
            if (r1 < cnt) {
                int tok = toks[row + 8];
                float gv = gts[row + 8];
                atomicAdd(&g_acc[(size_t)tok * D_DIM + d],     gv * expf(acc[mt][nt][2] + bb0));
                atomicAdd(&g_acc[(size_t)tok * D_DIM + d + 1], gv * expf(acc[mt][nt][3] + bb1));
            }
        }
    }
}

// ---- finalize: log with eps floor ----
__global__ void k_fin(float* __restrict__ out) {
    size_t i = (size_t)blockIdx.x * blockDim.x + threadIdx.x;
    if (i < (size_t)N_TOK * D_DIM) {
        float a = g_acc[i];
        out[i] = logf(a == 0.f ? EPS_F : a);
    }
}

extern "C" void kernel_launch(void* const* d_in, const int* in_sizes, int n_in,
                              void* d_out, int out_size) {
    const float* x  = (const float*)d_in[0];
    const float* Wg = (const float*)d_in[1];
    const float* W1 = (const float*)d_in[2];
    const float* b1 = (const float*)d_in[3];
    const float* W2 = (const float*)d_in[4];
    const float* b2 = (const float*)d_in[5];
    float* out = (float*)d_out;

    int nElem = N_TOK * D_DIM;

    k_init<<<(nElem + 255) / 256, 256>>>();
    k_gate<<<(N_TOK * 32 + 255) / 256, 256>>>(x, Wg);
    k_off<<<1, 32>>>();
    k_scatter<<<(N_TOK + 255) / 256, 256>>>();

    k_gemm1<<<dim3(N_TOK / BM, F_DIM / BN, E_NUM), THREADS>>>(x, W1, b1);
    k_gemm2<<<dim3(N_TOK / BM, D_DIM / BN, E_NUM), THREADS>>>(W2, b2);

    k_fin<<<(nElem + 255) / 256, 256>>>(out);
}